// round 5
// baseline (speedup 1.0000x reference)
#include <cuda_runtime.h>
#include <math_constants.h>

typedef unsigned long long ull;

#define B_ 2
#define T_ 256
#define E_ 512
#define H_ 8
#define D_ 64
#define AW_OFF (B_*T_*E_)

// scratch (allocation-free: device globals)
__device__ float g_q[B_*H_*T_*D_];        // [b][h][t][pp][4] : (e_p, e_p+16, o_p, o_p+16)
__device__ float g_k[B_*H_*16*T_*4];      // [b][h][pp][s][4] : transposed, coalesced in s
__device__ float g_v[B_*H_*T_*D_];        // natural [b][h][s][d]
__device__ float g_o[B_*T_*E_];           // [b*T+t][h*64+d]

// ---- packed f32x2 helpers -------------------------------------------------
__device__ __forceinline__ ull pk2(float lo, float hi) {
    ull r; asm("mov.b64 %0,{%1,%2};" : "=l"(r) : "f"(lo), "f"(hi)); return r;
}
__device__ __forceinline__ void upk2(ull v, float& a, float& b) {
    asm("mov.b64 {%0,%1},%2;" : "=f"(a), "=f"(b) : "l"(v));
}
__device__ __forceinline__ ull ffma2(ull a, ull b, ull c) {
    ull d; asm("fma.rn.f32x2 %0,%1,%2,%3;" : "=l"(d) : "l"(a), "l"(b), "l"(c)); return d;
}
__device__ __forceinline__ ull fmul2(ull a, ull b) {
    ull d; asm("mul.rn.f32x2 %0,%1,%2;" : "=l"(d) : "l"(a), "l"(b)); return d;
}
__device__ __forceinline__ ull fadd2(ull a, ull b) {
    ull d; asm("add.rn.f32x2 %0,%1,%2;" : "=l"(d) : "l"(a), "l"(b)); return d;
}

// ---------------------------------------------------------------------------
// GEMM: C = A(512x512) @ W(512xN) + bias. 256 threads, BMx64 tile, BK=16,
// double-buffered smem, microtile TM x 4 (2 packed n-pairs).
// mode 0: A = x, N = 1536, scatter to g_q/g_k/g_v. mode 1: A = g_o, write Cout.
// ---------------------------------------------------------------------------
template<int BM, int TM>
__global__ __launch_bounds__(256) void gemm_kernel(const float* __restrict__ A,
                            const float* __restrict__ W,
                            const float* __restrict__ bias,
                            float* __restrict__ Cout,
                            int N, int mode)
{
    __shared__ float As[2][16][BM + 4];
    __shared__ float Bs[2][16][64];

    const float* Asrc = (mode == 1) ? g_o : A;

    int tid = threadIdx.x;
    int tx = tid & 15;         // 16 col-groups of 4 (2 packed pairs)
    int ty = tid >> 4;         // 16 row-groups of TM
    int m0 = blockIdx.y * BM, n0 = blockIdx.x * 64;

    int arow = tid >> 2, ac4 = (tid & 3) * 4;   // A loader (arow < BM active)
    int brow = tid >> 4, bc4 = (tid & 15) * 4;  // B loader

    ull acc[TM][2];
#pragma unroll
    for (int i = 0; i < TM; i++) { acc[i][0] = pk2(0.f, 0.f); acc[i][1] = acc[i][0]; }

    float4 ra, rb;
    if (arow < BM) ra = *(const float4*)&Asrc[(size_t)(m0 + arow) * 512 + ac4];
    rb = *(const float4*)&W[(size_t)brow * N + n0 + bc4];
    if (arow < BM) {
        As[0][ac4 + 0][arow] = ra.x; As[0][ac4 + 1][arow] = ra.y;
        As[0][ac4 + 2][arow] = ra.z; As[0][ac4 + 3][arow] = ra.w;
    }
    *(float4*)&Bs[0][brow][bc4] = rb;
    __syncthreads();

    for (int kt16 = 0; kt16 < 32; kt16++) {
        int cur = kt16 & 1;
        if (kt16 < 31) {
            int kt = (kt16 + 1) * 16;
            if (arow < BM) ra = *(const float4*)&Asrc[(size_t)(m0 + arow) * 512 + kt + ac4];
            rb = *(const float4*)&W[(size_t)(kt + brow) * N + n0 + bc4];
        }
#pragma unroll
        for (int kk = 0; kk < 16; kk++) {
            float ar[TM];
            if (TM == 4) {
                float4 a4 = *(const float4*)&As[cur][kk][ty * 4];
                ar[0] = a4.x; ar[1] = a4.y; ar[2] = a4.z; ar[3] = a4.w;
            } else {
                float2 a2 = *(const float2*)&As[cur][kk][ty * 2];
                ar[0] = a2.x; ar[1] = a2.y;
            }
            double2 b2 = *(const double2*)&Bs[cur][kk][tx * 4];
            ull bp0 = __double_as_longlong(b2.x);
            ull bp1 = __double_as_longlong(b2.y);
#pragma unroll
            for (int i = 0; i < TM; i++) {
                ull ad = pk2(ar[i], ar[i]);
                acc[i][0] = ffma2(ad, bp0, acc[i][0]);
                acc[i][1] = ffma2(ad, bp1, acc[i][1]);
            }
        }
        if (kt16 < 31) {
            int nxt = cur ^ 1;
            if (arow < BM) {
                As[nxt][ac4 + 0][arow] = ra.x; As[nxt][ac4 + 1][arow] = ra.y;
                As[nxt][ac4 + 2][arow] = ra.z; As[nxt][ac4 + 3][arow] = ra.w;
            }
            *(float4*)&Bs[nxt][brow][bc4] = rb;
        }
        __syncthreads();
    }

    if (mode == 1) {
#pragma unroll
        for (int i = 0; i < TM; i++) {
            int m = m0 + ty * TM + i;
#pragma unroll
            for (int j = 0; j < 2; j++) {
                float x, y; upk2(acc[i][j], x, y);
                int n = n0 + tx * 4 + j * 2;
                Cout[(size_t)m * N + n]     = x + bias[n];
                Cout[(size_t)m * N + n + 1] = y + bias[n + 1];
            }
        }
    } else {
        int which = n0 >> 9;               // 0=q 1=k 2=v
        int h = (n0 & 511) >> 6;
#pragma unroll
        for (int i = 0; i < TM; i++) {
            int m = m0 + ty * TM + i;
            int b = m >> 8, t = m & 255;
#pragma unroll
            for (int j = 0; j < 2; j++) {
                float x, y; upk2(acc[i][j], x, y);
#pragma unroll
                for (int u = 0; u < 2; u++) {
                    int d = tx * 4 + j * 2 + u;
                    float val = (u ? y : x) + bias[n0 + d];
                    if (which == 2) {
                        g_v[(((size_t)(b * H_ + h) * T_ + t) * D_) + d] = val;
                    } else {
                        int p = d >> 1, cmp = d & 1;
                        int pp = p & 15, hf = p >> 4;
                        if (which == 0)
                            g_q[(((size_t)(b * H_ + h) * T_ + t) * D_) + pp * 4 + cmp * 2 + hf] = val;
                        else
                            g_k[((((size_t)(b * H_ + h) * 16 + pp) * T_) + t) * 4 + cmp * 2 + hf] = val;
                    }
                }
            }
        }
    }
}

// ---------------------------------------------------------------------------
// Fused rotary attention. grid = 128: (b, 4 t-rows). 512 threads:
// warp = (g, h): head h, t-rows {2g, 2g+1}. lanes = s within chunk of 32.
// m register-prefetched into single smem buffer; A*V via smem-a broadcast.
// Score per pair p:  m_e*(q_e k_e + q_o k_o) + m_o*(q_o k_e - q_e k_o)
// ---------------------------------------------------------------------------
__global__ __launch_bounds__(512) void attn_kernel(const float* __restrict__ mglob,
                            const float* __restrict__ pad,
                            float* __restrict__ outw)
{
    __shared__ ull m_s[4][16][2][32];     // 32 KB, lane-major, conflict-free LDS.64
    __shared__ float4 q4_s[8][4][16];     // 8 KB
    __shared__ ull   qen_s[8][4][16];     // 4 KB  (-e, -e16)
    float* av_s = (float*)m_s;            // reused as av[4tt][8h][256s] after scores

    int tid = threadIdx.x;
    int sl = tid & 31;
    int h  = (tid >> 5) & 7;
    int g  = tid >> 8;
    int b  = blockIdx.x >> 6;
    int t0 = (blockIdx.x & 63) * 4;

    // stage q once: 512 items = 8h x 4tt x 16pp
    {
        int hh = tid >> 6, tt = (tid >> 4) & 3, pp = tid & 15;
        float4 f = *(const float4*)&g_q[(((size_t)(b * H_ + hh) * T_) + (t0 + tt)) * D_ + pp * 4];
        q4_s[hh][tt][pp] = f;
        qen_s[hh][tt][pp] = pk2(-f.x, -f.y);   // negated EVEN components
    }

    const double2* kT = (const double2*)g_k + (size_t)(b * H_ + h) * 16 * T_;
    const float*   vbase = g_v + (size_t)(b * H_ + h) * T_ * D_;
    const float*   mbase = mglob + (size_t)(b * T_ + t0) * T_ * D_;

    // m staging loader indices (2 items/thread: 1024 = 4tt x 32si x 8j4h)
    int j4h_[2], si_[2], tt_[2];
#pragma unroll
    for (int it = 0; it < 2; it++) {
        int idx = it * 512 + tid;
        j4h_[it] = idx & 7; si_[it] = (idx >> 3) & 31; tt_[it] = idx >> 8;
    }

    float4 rv1[2], rv2[2];
#pragma unroll
    for (int it = 0; it < 2; it++) {   // prefetch chunk 0
        const float* row = mbase + ((size_t)tt_[it] * T_ + si_[it]) * D_;
        rv1[it] = *(const float4*)(row + j4h_[it] * 4);
        rv2[it] = *(const float4*)(row + (j4h_[it] + 8) * 4);
    }

    int tta = 2 * g, ttb = 2 * g + 1;
    float sc[2][8];

#pragma unroll
    for (int c = 0; c < 8; c++) {
        __syncthreads();                // prev chunk's m_s reads done
#pragma unroll
        for (int it = 0; it < 2; it++) {
            int p0 = 2 * j4h_[it], p1 = p0 + 1, tt = tt_[it], si = si_[it];
            m_s[tt][p0][0][si] = pk2(rv1[it].x, rv2[it].x);
            m_s[tt][p0][1][si] = pk2(rv1[it].y, rv2[it].y);
            m_s[tt][p1][0][si] = pk2(rv1[it].z, rv2[it].z);
            m_s[tt][p1][1][si] = pk2(rv1[it].w, rv2[it].w);
        }
        if (c < 7) {                    // prefetch next chunk (overlaps compute)
#pragma unroll
            for (int it = 0; it < 2; it++) {
                const float* row = mbase + ((size_t)tt_[it] * T_ + (c + 1) * 32 + si_[it]) * D_;
                rv1[it] = *(const float4*)(row + j4h_[it] * 4);
                rv2[it] = *(const float4*)(row + (j4h_[it] + 8) * 4);
            }
        }
        __syncthreads();                // m_s (and on c=0, q_s) published

        int s = c * 32 + sl;
        float pm = pad[b * T_ + s];
        ull a0 = pk2(0.f, 0.f), a1 = a0;
#pragma unroll
        for (int pp = 0; pp < 16; pp++) {
            double2 kd = kT[pp * T_ + s];       // coalesced in s; L1-dedup across g pair
            ull ke = __double_as_longlong(kd.x);
            ull ko = __double_as_longlong(kd.y);
            {
                double2 q2 = *(const double2*)&q4_s[h][tta][pp];
                ull qe = __double_as_longlong(q2.x);
                ull qo = __double_as_longlong(q2.y);
                ull qen = qen_s[h][tta][pp];
                ull me = m_s[tta][pp][0][sl];
                ull mo = m_s[tta][pp][1][sl];
                ull cc = ffma2(qo, ko, fmul2(qe, ke));   // q_e k_e + q_o k_o
                ull dd = ffma2(qen, ko, fmul2(qo, ke));  // q_o k_e - q_e k_o
                a0 = ffma2(me, cc, a0);
                a0 = ffma2(mo, dd, a0);
            }
            {
                double2 q2 = *(const double2*)&q4_s[h][ttb][pp];
                ull qe = __double_as_longlong(q2.x);
                ull qo = __double_as_longlong(q2.y);
                ull qen = qen_s[h][ttb][pp];
                ull me = m_s[ttb][pp][0][sl];
                ull mo = m_s[ttb][pp][1][sl];
                ull cc = ffma2(qo, ko, fmul2(qe, ke));
                ull dd = ffma2(qen, ko, fmul2(qo, ke));
                a1 = ffma2(me, cc, a1);
                a1 = ffma2(mo, dd, a1);
            }
        }
        float x, y;
        upk2(a0, x, y); sc[0][c] = (x + y) * 0.125f + pm;
        upk2(a1, x, y); sc[1][c] = (x + y) * 0.125f + pm;
    }

    // softmax: row (tt,h) lives in one warp (32 lanes x 8 chunks)
    const unsigned FULL = 0xffffffffu;
    float aval[2][8];
#pragma unroll
    for (int u = 0; u < 2; u++) {
        float mx = -CUDART_INF_F;
#pragma unroll
        for (int c = 0; c < 8; c++) mx = fmaxf(mx, sc[u][c]);
#pragma unroll
        for (int o = 16; o > 0; o >>= 1) mx = fmaxf(mx, __shfl_xor_sync(FULL, mx, o));
        float sum = 0.f;
#pragma unroll
        for (int c = 0; c < 8; c++) {
            float e = __expf(sc[u][c] - mx);
            aval[u][c] = e;
            sum += e;
        }
#pragma unroll
        for (int o = 16; o > 0; o >>= 1) sum += __shfl_xor_sync(FULL, sum, o);
        float r = 1.f / sum;
#pragma unroll
        for (int c = 0; c < 8; c++) aval[u][c] *= r;
    }

    // publish a to smem (reuses m_s; score reads finished)
    __syncthreads();
#pragma unroll
    for (int u = 0; u < 2; u++)
#pragma unroll
        for (int c = 0; c < 8; c++)
            av_s[((2 * g + u) * 8 + h) * 256 + c * 32 + sl] = aval[u][c];
    __syncthreads();

    // o = a @ v : lane owns d = {2sl,2sl+1}; a via warp-uniform LDS broadcast
    const float* avh0 = av_s + (tta * 8 + h) * 256;
    const float* avh1 = av_s + (ttb * 8 + h) * 256;
    ull o0a = pk2(0.f, 0.f), o0b = o0a, o1a = o0a, o1b = o0a;
#pragma unroll 4
    for (int s2 = 0; s2 < 256; s2 += 2) {
        ull v0 = *(const ull*)(vbase + (size_t)s2 * D_ + 2 * sl);
        ull v1 = *(const ull*)(vbase + (size_t)(s2 + 1) * D_ + 2 * sl);
        float a00 = avh0[s2], a01 = avh0[s2 + 1];
        float a10 = avh1[s2], a11 = avh1[s2 + 1];
        o0a = ffma2(pk2(a00, a00), v0, o0a);
        o0b = ffma2(pk2(a01, a01), v1, o0b);
        o1a = ffma2(pk2(a10, a10), v0, o1a);
        o1b = ffma2(pk2(a11, a11), v1, o1b);
    }
    ull oa0 = fadd2(o0a, o0b), oa1 = fadd2(o1a, o1b);
    *(ull*)&g_o[((size_t)(b * T_ + t0 + tta) * H_ + h) * D_ + 2 * sl] = oa0;
    *(ull*)&g_o[((size_t)(b * T_ + t0 + ttb) * H_ + h) * D_ + 2 * sl] = oa1;

    // attn_weights: 1024 outputs (4tt x 256s) / 512 threads = 2 each
#pragma unroll
    for (int it = 0; it < 2; it++) {
        int idx = it * 512 + tid;
        int tt = idx >> 8, s5 = idx & 255;
        float acc = 0.f;
#pragma unroll
        for (int hh = 0; hh < 8; hh++) acc += av_s[(tt * 8 + hh) * 256 + s5];
        outw[AW_OFF + (size_t)(b * T_ + t0 + tt) * T_ + s5] = acc * 0.125f;
    }
}

// ---------------------------------------------------------------------------
extern "C" void kernel_launch(void* const* d_in, const int* in_sizes, int n_in,
                              void* d_out, int out_size)
{
    const float* x    = (const float*)d_in[0];
    const float* am   = (const float*)d_in[1];
    const float* pm   = (const float*)d_in[2];
    const float* Wqkv = (const float*)d_in[3];
    const float* bqkv = (const float*)d_in[4];
    const float* Wo   = (const float*)d_in[5];
    const float* bo   = (const float*)d_in[6];
    float* out = (float*)d_out;

    gemm_kernel<32, 2><<<dim3(24, 16), 256>>>(x, Wqkv, bqkv, nullptr, 1536, 0);
    attn_kernel<<<128, 512>>>(am, pm, out);
    gemm_kernel<32, 2><<<dim3(8, 16), 256>>>(nullptr, Wo, bo, out, 512, 1);
}

// round 6
// speedup vs baseline: 1.2277x; 1.2277x over previous
#include <cuda_runtime.h>
#include <math_constants.h>

typedef unsigned long long ull;

#define B_ 2
#define T_ 256
#define E_ 512
#define H_ 8
#define D_ 64
#define AW_OFF (B_*T_*E_)

// scratch (allocation-free: device globals)
__device__ float g_q[B_*H_*T_*D_];        // [b][h][t][pp][4] : (e_p, e_p+16, o_p, o_p+16)
__device__ float g_k[B_*H_*16*T_*4];      // [b][h][pp][s][4] : transposed, coalesced in s
__device__ float g_v[B_*H_*T_*D_];        // natural [b][h][s][d]
__device__ float g_o[B_*T_*E_];           // [b*T+t][h*64+d]

// ---- packed f32x2 helpers -------------------------------------------------
__device__ __forceinline__ ull pk2(float lo, float hi) {
    ull r; asm("mov.b64 %0,{%1,%2};" : "=l"(r) : "f"(lo), "f"(hi)); return r;
}
__device__ __forceinline__ void upk2(ull v, float& a, float& b) {
    asm("mov.b64 {%0,%1},%2;" : "=f"(a), "=f"(b) : "l"(v));
}
__device__ __forceinline__ ull ffma2(ull a, ull b, ull c) {
    ull d; asm("fma.rn.f32x2 %0,%1,%2,%3;" : "=l"(d) : "l"(a), "l"(b), "l"(c)); return d;
}
__device__ __forceinline__ ull fmul2(ull a, ull b) {
    ull d; asm("mul.rn.f32x2 %0,%1,%2;" : "=l"(d) : "l"(a), "l"(b)); return d;
}
__device__ __forceinline__ ull fadd2(ull a, ull b) {
    ull d; asm("add.rn.f32x2 %0,%1,%2;" : "=l"(d) : "l"(a), "l"(b)); return d;
}

// ---------------------------------------------------------------------------
// GEMM: C = A @ W (+bias). 256 threads, BMx64 tile, BK=16, double-buffered,
// microtile TM x 4 cols (2 packed n-pairs).
// mode 0: N=1536, scatter to g_q/g_k/g_v (+bias).
// mode 1: N=512,  A=g_o, Cout = result + bias.
// mode 2: N=512,  A=g_o, split-K: atomicAdd into Cout (bias pre-filled).
// nk16: number of BK=16 steps; k-window base = blockIdx.z * nk16 * 16.
// ---------------------------------------------------------------------------
template<int BM, int TM>
__global__ __launch_bounds__(256) void gemm_kernel(const float* __restrict__ A,
                            const float* __restrict__ W,
                            const float* __restrict__ bias,
                            float* __restrict__ Cout,
                            int N, int mode, int nk16)
{
    __shared__ float As[2][16][BM + 4];
    __shared__ float Bs[2][16][64];

    const float* Asrc = (mode == 0) ? A : g_o;

    int tid = threadIdx.x;
    int tx = tid & 15;         // 16 col-groups of 4 (2 packed pairs)
    int ty = tid >> 4;         // 16 row-groups of TM
    int m0 = blockIdx.y * BM, n0 = blockIdx.x * 64;
    int kb = blockIdx.z * nk16 * 16;

    int arow = tid >> 2, ac4 = (tid & 3) * 4;   // A loader (arow < BM active)
    int brow = tid >> 4, bc4 = (tid & 15) * 4;  // B loader

    ull acc[TM][2];
#pragma unroll
    for (int i = 0; i < TM; i++) { acc[i][0] = pk2(0.f, 0.f); acc[i][1] = acc[i][0]; }

    float4 ra, rb;
    if (arow < BM) ra = *(const float4*)&Asrc[(size_t)(m0 + arow) * 512 + kb + ac4];
    rb = *(const float4*)&W[(size_t)(kb + brow) * N + n0 + bc4];
    if (arow < BM) {
        As[0][ac4 + 0][arow] = ra.x; As[0][ac4 + 1][arow] = ra.y;
        As[0][ac4 + 2][arow] = ra.z; As[0][ac4 + 3][arow] = ra.w;
    }
    *(float4*)&Bs[0][brow][bc4] = rb;
    __syncthreads();

    for (int kt16 = 0; kt16 < nk16; kt16++) {
        int cur = kt16 & 1;
        if (kt16 < nk16 - 1) {
            int kt = kb + (kt16 + 1) * 16;
            if (arow < BM) ra = *(const float4*)&Asrc[(size_t)(m0 + arow) * 512 + kt + ac4];
            rb = *(const float4*)&W[(size_t)(kt + brow) * N + n0 + bc4];
        }
#pragma unroll
        for (int kk = 0; kk < 16; kk++) {
            float ar[TM];
            if (TM == 4) {
                float4 a4 = *(const float4*)&As[cur][kk][ty * 4];
                ar[0] = a4.x; ar[1] = a4.y; ar[2] = a4.z; ar[3] = a4.w;
            } else {
                float2 a2 = *(const float2*)&As[cur][kk][ty * 2];
                ar[0] = a2.x; ar[1] = a2.y;
            }
            double2 b2 = *(const double2*)&Bs[cur][kk][tx * 4];
            ull bp0 = __double_as_longlong(b2.x);
            ull bp1 = __double_as_longlong(b2.y);
#pragma unroll
            for (int i = 0; i < TM; i++) {
                ull ad = pk2(ar[i], ar[i]);
                acc[i][0] = ffma2(ad, bp0, acc[i][0]);
                acc[i][1] = ffma2(ad, bp1, acc[i][1]);
            }
        }
        if (kt16 < nk16 - 1) {
            int nxt = cur ^ 1;
            if (arow < BM) {
                As[nxt][ac4 + 0][arow] = ra.x; As[nxt][ac4 + 1][arow] = ra.y;
                As[nxt][ac4 + 2][arow] = ra.z; As[nxt][ac4 + 3][arow] = ra.w;
            }
            *(float4*)&Bs[nxt][brow][bc4] = rb;
        }
        __syncthreads();
    }

    if (mode == 1) {
#pragma unroll
        for (int i = 0; i < TM; i++) {
            int m = m0 + ty * TM + i;
#pragma unroll
            for (int j = 0; j < 2; j++) {
                float x, y; upk2(acc[i][j], x, y);
                int n = n0 + tx * 4 + j * 2;
                Cout[(size_t)m * N + n]     = x + bias[n];
                Cout[(size_t)m * N + n + 1] = y + bias[n + 1];
            }
        }
    } else if (mode == 2) {
#pragma unroll
        for (int i = 0; i < TM; i++) {
            int m = m0 + ty * TM + i;
#pragma unroll
            for (int j = 0; j < 2; j++) {
                float x, y; upk2(acc[i][j], x, y);
                int n = n0 + tx * 4 + j * 2;
                atomicAdd(&Cout[(size_t)m * N + n],     x);
                atomicAdd(&Cout[(size_t)m * N + n + 1], y);
            }
        }
    } else {
        int which = n0 >> 9;               // 0=q 1=k 2=v
        int h = (n0 & 511) >> 6;
#pragma unroll
        for (int i = 0; i < TM; i++) {
            int m = m0 + ty * TM + i;
            int b = m >> 8, t = m & 255;
#pragma unroll
            for (int j = 0; j < 2; j++) {
                float x, y; upk2(acc[i][j], x, y);
#pragma unroll
                for (int u = 0; u < 2; u++) {
                    int d = tx * 4 + j * 2 + u;
                    float val = (u ? y : x) + bias[n0 + d];
                    if (which == 2) {
                        g_v[(((size_t)(b * H_ + h) * T_ + t) * D_) + d] = val;
                    } else {
                        int p = d >> 1, cmp = d & 1;
                        int pp = p & 15, hf = p >> 4;
                        if (which == 0)
                            g_q[(((size_t)(b * H_ + h) * T_ + t) * D_) + pp * 4 + cmp * 2 + hf] = val;
                        else
                            g_k[((((size_t)(b * H_ + h) * 16 + pp) * T_) + t) * 4 + cmp * 2 + hf] = val;
                    }
                }
            }
        }
    }
}

// ---------------------------------------------------------------------------
// init_out: pre-fill o-region of the output with the bias (for split-K atomics)
// ---------------------------------------------------------------------------
__global__ void init_out_kernel(const float* __restrict__ bo, float* __restrict__ out)
{
    int i = blockIdx.x * 256 + threadIdx.x;           // 65536 float4s
    ((float4*)out)[i] = ((const float4*)bo)[i & 127];
}

// ---------------------------------------------------------------------------
// Fused rotary attention. grid = 128: (b, 4 t-rows). 512 threads:
// warp = (g, h): head h, t-rows {2g, 2g+1}. lanes = s within chunk of 32.
// m register-prefetched; lane dim padded to 33 -> STS conflicts 8-way -> 2-way.
// Score per pair p:  m_e*(q_e k_e + q_o k_o) + m_o*(q_o k_e - q_e k_o)
// ---------------------------------------------------------------------------
__global__ __launch_bounds__(512) void attn_kernel(const float* __restrict__ mglob,
                            const float* __restrict__ pad,
                            float* __restrict__ outw)
{
    __shared__ ull m_s[4][16][2][33];     // 33.8 KB, padded lane dim
    __shared__ float4 q4_s[8][4][16];     // 8 KB
    __shared__ ull   qen_s[8][4][16];     // 4 KB  (-e, -e16)
    float* av_s = (float*)m_s;            // reused as av[4tt][8h][256s] (32KB fits)

    int tid = threadIdx.x;
    int sl = tid & 31;
    int h  = (tid >> 5) & 7;
    int g  = tid >> 8;
    int b  = blockIdx.x >> 6;
    int t0 = (blockIdx.x & 63) * 4;

    // stage q once: 512 items = 8h x 4tt x 16pp
    {
        int hh = tid >> 6, tt = (tid >> 4) & 3, pp = tid & 15;
        float4 f = *(const float4*)&g_q[(((size_t)(b * H_ + hh) * T_) + (t0 + tt)) * D_ + pp * 4];
        q4_s[hh][tt][pp] = f;
        qen_s[hh][tt][pp] = pk2(-f.x, -f.y);   // negated EVEN components
    }

    const double2* kT = (const double2*)g_k + (size_t)(b * H_ + h) * 16 * T_;
    const float*   vbase = g_v + (size_t)(b * H_ + h) * T_ * D_;
    const float*   mbase = mglob + (size_t)(b * T_ + t0) * T_ * D_;

    // m staging loader indices (2 items/thread: 1024 = 4tt x 32si x 8j4h)
    int j4h_[2], si_[2], tt_[2];
#pragma unroll
    for (int it = 0; it < 2; it++) {
        int idx = it * 512 + tid;
        j4h_[it] = idx & 7; si_[it] = (idx >> 3) & 31; tt_[it] = idx >> 8;
    }

    float4 rv1[2], rv2[2];
#pragma unroll
    for (int it = 0; it < 2; it++) {   // prefetch chunk 0
        const float* row = mbase + ((size_t)tt_[it] * T_ + si_[it]) * D_;
        rv1[it] = *(const float4*)(row + j4h_[it] * 4);
        rv2[it] = *(const float4*)(row + (j4h_[it] + 8) * 4);
    }

    int tta = 2 * g, ttb = 2 * g + 1;
    float sc[2][8];

#pragma unroll
    for (int c = 0; c < 8; c++) {
        __syncthreads();                // prev chunk's m_s reads done
#pragma unroll
        for (int it = 0; it < 2; it++) {
            int p0 = 2 * j4h_[it], p1 = p0 + 1, tt = tt_[it], si = si_[it];
            m_s[tt][p0][0][si] = pk2(rv1[it].x, rv2[it].x);
            m_s[tt][p0][1][si] = pk2(rv1[it].y, rv2[it].y);
            m_s[tt][p1][0][si] = pk2(rv1[it].z, rv2[it].z);
            m_s[tt][p1][1][si] = pk2(rv1[it].w, rv2[it].w);
        }
        if (c < 7) {                    // prefetch next chunk (overlaps compute)
#pragma unroll
            for (int it = 0; it < 2; it++) {
                const float* row = mbase + ((size_t)tt_[it] * T_ + (c + 1) * 32 + si_[it]) * D_;
                rv1[it] = *(const float4*)(row + j4h_[it] * 4);
                rv2[it] = *(const float4*)(row + (j4h_[it] + 8) * 4);
            }
        }
        __syncthreads();                // m_s (and on c=0, q_s) published

        int s = c * 32 + sl;
        float pm = pad[b * T_ + s];
        ull a0 = pk2(0.f, 0.f), a1 = a0;
#pragma unroll
        for (int pp = 0; pp < 16; pp++) {
            double2 kd = kT[pp * T_ + s];       // coalesced in s
            ull ke = __double_as_longlong(kd.x);
            ull ko = __double_as_longlong(kd.y);
            {
                double2 q2 = *(const double2*)&q4_s[h][tta][pp];
                ull qe = __double_as_longlong(q2.x);
                ull qo = __double_as_longlong(q2.y);
                ull qen = qen_s[h][tta][pp];
                ull me = m_s[tta][pp][0][sl];
                ull mo = m_s[tta][pp][1][sl];
                ull cc = ffma2(qo, ko, fmul2(qe, ke));   // q_e k_e + q_o k_o
                ull dd = ffma2(qen, ko, fmul2(qo, ke));  // q_o k_e - q_e k_o
                a0 = ffma2(me, cc, a0);
                a0 = ffma2(mo, dd, a0);
            }
            {
                double2 q2 = *(const double2*)&q4_s[h][ttb][pp];
                ull qe = __double_as_longlong(q2.x);
                ull qo = __double_as_longlong(q2.y);
                ull qen = qen_s[h][ttb][pp];
                ull me = m_s[ttb][pp][0][sl];
                ull mo = m_s[ttb][pp][1][sl];
                ull cc = ffma2(qo, ko, fmul2(qe, ke));
                ull dd = ffma2(qen, ko, fmul2(qo, ke));
                a1 = ffma2(me, cc, a1);
                a1 = ffma2(mo, dd, a1);
            }
        }
        float x, y;
        upk2(a0, x, y); sc[0][c] = (x + y) * 0.125f + pm;
        upk2(a1, x, y); sc[1][c] = (x + y) * 0.125f + pm;
    }

    // softmax: row (tt,h) lives in one warp (32 lanes x 8 chunks)
    const unsigned FULL = 0xffffffffu;
    float aval[2][8];
#pragma unroll
    for (int u = 0; u < 2; u++) {
        float mx = -CUDART_INF_F;
#pragma unroll
        for (int c = 0; c < 8; c++) mx = fmaxf(mx, sc[u][c]);
#pragma unroll
        for (int o = 16; o > 0; o >>= 1) mx = fmaxf(mx, __shfl_xor_sync(FULL, mx, o));
        float sum = 0.f;
#pragma unroll
        for (int c = 0; c < 8; c++) {
            float e = __expf(sc[u][c] - mx);
            aval[u][c] = e;
            sum += e;
        }
#pragma unroll
        for (int o = 16; o > 0; o >>= 1) sum += __shfl_xor_sync(FULL, sum, o);
        float r = 1.f / sum;
#pragma unroll
        for (int c = 0; c < 8; c++) aval[u][c] *= r;
    }

    // publish a to smem (reuses m_s storage; score reads finished)
    __syncthreads();
#pragma unroll
    for (int u = 0; u < 2; u++)
#pragma unroll
        for (int c = 0; c < 8; c++)
            av_s[((2 * g + u) * 8 + h) * 256 + c * 32 + sl] = aval[u][c];
    __syncthreads();

    // o = a @ v : lane owns d = {2sl,2sl+1}; a via warp-uniform LDS broadcast
    const float* avh0 = av_s + (tta * 8 + h) * 256;
    const float* avh1 = av_s + (ttb * 8 + h) * 256;
    ull o0a = pk2(0.f, 0.f), o0b = o0a, o1a = o0a, o1b = o0a;
#pragma unroll 4
    for (int s2 = 0; s2 < 256; s2 += 2) {
        ull v0 = *(const ull*)(vbase + (size_t)s2 * D_ + 2 * sl);
        ull v1 = *(const ull*)(vbase + (size_t)(s2 + 1) * D_ + 2 * sl);
        float a00 = avh0[s2], a01 = avh0[s2 + 1];
        float a10 = avh1[s2], a11 = avh1[s2 + 1];
        o0a = ffma2(pk2(a00, a00), v0, o0a);
        o0b = ffma2(pk2(a01, a01), v1, o0b);
        o1a = ffma2(pk2(a10, a10), v0, o1a);
        o1b = ffma2(pk2(a11, a11), v1, o1b);
    }
    ull oa0 = fadd2(o0a, o0b), oa1 = fadd2(o1a, o1b);
    *(ull*)&g_o[((size_t)(b * T_ + t0 + tta) * H_ + h) * D_ + 2 * sl] = oa0;
    *(ull*)&g_o[((size_t)(b * T_ + t0 + ttb) * H_ + h) * D_ + 2 * sl] = oa1;

    // attn_weights: 1024 outputs (4tt x 256s) / 512 threads = 2 each
#pragma unroll
    for (int it = 0; it < 2; it++) {
        int idx = it * 512 + tid;
        int tt = idx >> 8, s5 = idx & 255;
        float acc = 0.f;
#pragma unroll
        for (int hh = 0; hh < 8; hh++) acc += av_s[(tt * 8 + hh) * 256 + s5];
        outw[AW_OFF + (size_t)(b * T_ + t0 + tt) * T_ + s5] = acc * 0.125f;
    }
}

// ---------------------------------------------------------------------------
extern "C" void kernel_launch(void* const* d_in, const int* in_sizes, int n_in,
                              void* d_out, int out_size)
{
    const float* x    = (const float*)d_in[0];
    const float* am   = (const float*)d_in[1];
    const float* pm   = (const float*)d_in[2];
    const float* Wqkv = (const float*)d_in[3];
    const float* bqkv = (const float*)d_in[4];
    const float* Wo   = (const float*)d_in[5];
    const float* bo   = (const float*)d_in[6];
    float* out = (float*)d_out;

    // 1: QKV projection + head scatter
    gemm_kernel<64, 4><<<dim3(24, 8, 1), 256>>>(x, Wqkv, bqkv, nullptr, 1536, 0, 32);
    // 2: fused rotary attention (+ attn_weights region of output)
    attn_kernel<<<128, 512>>>(am, pm, out);
    // 3: pre-fill o-region with bias (split-K target)
    init_out_kernel<<<256, 256>>>(bo, out);
    // 4: output projection, split-K=2, atomic accumulate
    gemm_kernel<64, 4><<<dim3(8, 8, 2), 256>>>(nullptr, Wo, bo, out, 512, 2, 16);
}

// round 12
// speedup vs baseline: 1.3020x; 1.0605x over previous
#include <cuda_runtime.h>
#include <math_constants.h>

typedef unsigned long long ull;

#define B_ 2
#define T_ 256
#define E_ 512
#define H_ 8
#define D_ 64
#define AW_OFF (B_*T_*E_)

// scratch (allocation-free: device globals)
__device__ float g_q[B_*H_*T_*D_];        // [b][h][t][pp][4] : (e_p, e_p+16, o_p, o_p+16)
__device__ float g_k[B_*H_*16*T_*4];      // [b][h][pp][s][4] : transposed, coalesced in s
__device__ float g_v[B_*H_*T_*D_];        // natural [b][h][s][d]
__device__ float g_o[B_*T_*E_];           // [b*T+t][h*64+d]

// ---- packed f32x2 helpers -------------------------------------------------
__device__ __forceinline__ ull pk2(float lo, float hi) {
    ull r; asm("mov.b64 %0,{%1,%2};" : "=l"(r) : "f"(lo), "f"(hi)); return r;
}
__device__ __forceinline__ void upk2(ull v, float& a, float& b) {
    asm("mov.b64 {%0,%1},%2;" : "=f"(a), "=f"(b) : "l"(v));
}
__device__ __forceinline__ ull ffma2(ull a, ull b, ull c) {
    ull d; asm("fma.rn.f32x2 %0,%1,%2,%3;" : "=l"(d) : "l"(a), "l"(b), "l"(c)); return d;
}
__device__ __forceinline__ ull fmul2(ull a, ull b) {
    ull d; asm("mul.rn.f32x2 %0,%1,%2;" : "=l"(d) : "l"(a), "l"(b)); return d;
}
__device__ __forceinline__ ull fadd2(ull a, ull b) {
    ull d; asm("add.rn.f32x2 %0,%1,%2;" : "=l"(d) : "l"(a), "l"(b)); return d;
}

// ---------------------------------------------------------------------------
// init_qkv: pre-fill g_q/g_k/g_v with bias in their scattered layouts
// (split-K gemm1 accumulates into them with atomics). 262144 threads.
// ---------------------------------------------------------------------------
__global__ void init_qkv_kernel(const float* __restrict__ bqkv)
{
    int idx = blockIdx.x * 256 + threadIdx.x;      // ((b*8+h)*256+t)*64+d
    int d = idx & 63;
    int h = (idx >> 14) & 7;
    int hd = h * 64 + d;
    g_v[idx] = bqkv[1024 + hd];
    int base = idx & ~63;                           // ((b*8+h)*256+t)*64
    int p = d >> 1, cmp = d & 1, pp = p & 15, hf = p >> 4;
    g_q[base + pp * 4 + cmp * 2 + hf] = bqkv[hd];
    int t = (idx >> 6) & 255;
    int bh = idx >> 14;                             // b*8+h
    g_k[((bh * 16 + pp) * 256 + t) * 4 + cmp * 2 + hf] = bqkv[512 + hd];
}

// ---------------------------------------------------------------------------
// init_out: pre-fill o-region of output with bias (split-K atomic target)
// ---------------------------------------------------------------------------
__global__ void init_out_kernel(const float* __restrict__ bo, float* __restrict__ out)
{
    int i = blockIdx.x * 256 + threadIdx.x;         // 65536 float4s
    ((float4*)out)[i] = ((const float4*)bo)[i & 127];
}

// ---------------------------------------------------------------------------
// GEMM: C = A @ W. 256 threads, BMx64 tile, BK=16, double-buffered smem,
// microtile TM x 4 cols (2 packed n-pairs). Split-K: kb = blockIdx.z*nk16*16.
// mode 2: atomicAdd into Cout (N=512, A=g_o; bias pre-filled by init_out).
// mode 3: atomicAdd scatter into g_q/g_k/g_v (N=1536; bias via init_qkv).
// ---------------------------------------------------------------------------
template<int BM, int TM>
__global__ __launch_bounds__(256) void gemm_kernel(const float* __restrict__ A,
                            const float* __restrict__ W,
                            float* __restrict__ Cout,
                            int N, int mode, int nk16)
{
    __shared__ float As[2][16][BM + 4];
    __shared__ float Bs[2][16][64];

    const float* Asrc = (mode == 3) ? A : g_o;

    int tid = threadIdx.x;
    int tx = tid & 15;         // 16 col-groups of 4 (2 packed pairs)
    int ty = tid >> 4;         // 16 row-groups of TM
    int m0 = blockIdx.y * BM, n0 = blockIdx.x * 64;
    int kb = blockIdx.z * nk16 * 16;

    int arow = tid >> 2, ac4 = (tid & 3) * 4;   // A loader (arow < BM active)
    int brow = tid >> 4, bc4 = (tid & 15) * 4;  // B loader

    ull acc[TM][2];
#pragma unroll
    for (int i = 0; i < TM; i++) { acc[i][0] = pk2(0.f, 0.f); acc[i][1] = acc[i][0]; }

    float4 ra, rb;
    if (arow < BM) ra = *(const float4*)&Asrc[(size_t)(m0 + arow) * 512 + kb + ac4];
    rb = *(const float4*)&W[(size_t)(kb + brow) * N + n0 + bc4];
    if (arow < BM) {
        As[0][ac4 + 0][arow] = ra.x; As[0][ac4 + 1][arow] = ra.y;
        As[0][ac4 + 2][arow] = ra.z; As[0][ac4 + 3][arow] = ra.w;
    }
    *(float4*)&Bs[0][brow][bc4] = rb;
    __syncthreads();

    for (int kt16 = 0; kt16 < nk16; kt16++) {
        int cur = kt16 & 1;
        if (kt16 < nk16 - 1) {
            int kt = kb + (kt16 + 1) * 16;
            if (arow < BM) ra = *(const float4*)&Asrc[(size_t)(m0 + arow) * 512 + kt + ac4];
            rb = *(const float4*)&W[(size_t)(kt + brow) * N + n0 + bc4];
        }
#pragma unroll
        for (int kk = 0; kk < 16; kk++) {
            float ar[TM];
            if (TM == 4) {
                float4 a4 = *(const float4*)&As[cur][kk][ty * 4];
                ar[0] = a4.x; ar[1] = a4.y; ar[2] = a4.z; ar[3] = a4.w;
            } else {
                float2 a2 = *(const float2*)&As[cur][kk][ty * 2];
                ar[0] = a2.x; ar[1] = a2.y;
            }
            double2 b2 = *(const double2*)&Bs[cur][kk][tx * 4];
            ull bp0 = __double_as_longlong(b2.x);
            ull bp1 = __double_as_longlong(b2.y);
#pragma unroll
            for (int i = 0; i < TM; i++) {
                ull ad = pk2(ar[i], ar[i]);
                acc[i][0] = ffma2(ad, bp0, acc[i][0]);
                acc[i][1] = ffma2(ad, bp1, acc[i][1]);
            }
        }
        if (kt16 < nk16 - 1) {
            int nxt = cur ^ 1;
            if (arow < BM) {
                As[nxt][ac4 + 0][arow] = ra.x; As[nxt][ac4 + 1][arow] = ra.y;
                As[nxt][ac4 + 2][arow] = ra.z; As[nxt][ac4 + 3][arow] = ra.w;
            }
            *(float4*)&Bs[nxt][brow][bc4] = rb;
        }
        __syncthreads();
    }

    if (mode == 2) {
#pragma unroll
        for (int i = 0; i < TM; i++) {
            int m = m0 + ty * TM + i;
#pragma unroll
            for (int j = 0; j < 2; j++) {
                float x, y; upk2(acc[i][j], x, y);
                int n = n0 + tx * 4 + j * 2;
                atomicAdd(&Cout[(size_t)m * N + n],     x);
                atomicAdd(&Cout[(size_t)m * N + n + 1], y);
            }
        }
    } else {
        int which = n0 >> 9;               // 0=q 1=k 2=v
        int h = (n0 & 511) >> 6;
#pragma unroll
        for (int i = 0; i < TM; i++) {
            int m = m0 + ty * TM + i;
            int b = m >> 8, t = m & 255;
#pragma unroll
            for (int j = 0; j < 2; j++) {
                float x, y; upk2(acc[i][j], x, y);
#pragma unroll
                for (int u = 0; u < 2; u++) {
                    int d = tx * 4 + j * 2 + u;
                    float val = u ? y : x;
                    if (which == 2) {
                        atomicAdd(&g_v[(((size_t)(b * H_ + h) * T_ + t) * D_) + d], val);
                    } else {
                        int p = d >> 1, cmp = d & 1;
                        int pp = p & 15, hf = p >> 4;
                        if (which == 0)
                            atomicAdd(&g_q[(((size_t)(b * H_ + h) * T_ + t) * D_) + pp * 4 + cmp * 2 + hf], val);
                        else
                            atomicAdd(&g_k[((((size_t)(b * H_ + h) * 16 + pp) * T_) + t) * 4 + cmp * 2 + hf], val);
                    }
                }
            }
        }
    }
}

// ---------------------------------------------------------------------------
// Fused rotary attention (identical to the R6 94.2us version).
// grid = 128: (b, 4 t-rows). 512 threads: warp = (g,h). s in 8 chunks of 32.
// Score per pair p:  m_e*(q_e k_e + q_o k_o) + m_o*(q_o k_e - q_e k_o)
// ---------------------------------------------------------------------------
__global__ __launch_bounds__(512) void attn_kernel(const float* __restrict__ mglob,
                            const float* __restrict__ pad,
                            float* __restrict__ outw)
{
    __shared__ ull m_s[4][16][2][33];     // padded lane dim: STS 8-way -> 2-way
    __shared__ float4 q4_s[8][4][16];
    __shared__ ull   qen_s[8][4][16];     // (-e, -e16)
    float* av_s = (float*)m_s;            // reused as av[4tt][8h][256s]

    int tid = threadIdx.x;
    int sl = tid & 31;
    int h  = (tid >> 5) & 7;
    int g  = tid >> 8;
    int b  = blockIdx.x >> 6;
    int t0 = (blockIdx.x & 63) * 4;

    {
        int hh = tid >> 6, tt = (tid >> 4) & 3, pp = tid & 15;
        float4 f = *(const float4*)&g_q[(((size_t)(b * H_ + hh) * T_) + (t0 + tt)) * D_ + pp * 4];
        q4_s[hh][tt][pp] = f;
        qen_s[hh][tt][pp] = pk2(-f.x, -f.y);
    }

    const double2* kT = (const double2*)g_k + (size_t)(b * H_ + h) * 16 * T_;
    const float*   vbase = g_v + (size_t)(b * H_ + h) * T_ * D_;
    const float*   mbase = mglob + (size_t)(b * T_ + t0) * T_ * D_;

    int j4h_[2], si_[2], tt_[2];
#pragma unroll
    for (int it = 0; it < 2; it++) {
        int idx = it * 512 + tid;
        j4h_[it] = idx & 7; si_[it] = (idx >> 3) & 31; tt_[it] = idx >> 8;
    }

    float4 rv1[2], rv2[2];
#pragma unroll
    for (int it = 0; it < 2; it++) {
        const float* row = mbase + ((size_t)tt_[it] * T_ + si_[it]) * D_;
        rv1[it] = *(const float4*)(row + j4h_[it] * 4);
        rv2[it] = *(const float4*)(row + (j4h_[it] + 8) * 4);
    }

    int tta = 2 * g, ttb = 2 * g + 1;
    float sc[2][8];

#pragma unroll
    for (int c = 0; c < 8; c++) {
        __syncthreads();
#pragma unroll
        for (int it = 0; it < 2; it++) {
            int p0 = 2 * j4h_[it], p1 = p0 + 1, tt = tt_[it], si = si_[it];
            m_s[tt][p0][0][si] = pk2(rv1[it].x, rv2[it].x);
            m_s[tt][p0][1][si] = pk2(rv1[it].y, rv2[it].y);
            m_s[tt][p1][0][si] = pk2(rv1[it].z, rv2[it].z);
            m_s[tt][p1][1][si] = pk2(rv1[it].w, rv2[it].w);
        }
        if (c < 7) {
#pragma unroll
            for (int it = 0; it < 2; it++) {
                const float* row = mbase + ((size_t)tt_[it] * T_ + (c + 1) * 32 + si_[it]) * D_;
                rv1[it] = *(const float4*)(row + j4h_[it] * 4);
                rv2[it] = *(const float4*)(row + (j4h_[it] + 8) * 4);
            }
        }
        __syncthreads();

        int s = c * 32 + sl;
        float pm = pad[b * T_ + s];
        ull a0 = pk2(0.f, 0.f), a1 = a0;
#pragma unroll
        for (int pp = 0; pp < 16; pp++) {
            double2 kd = kT[pp * T_ + s];
            ull ke = __double_as_longlong(kd.x);
            ull ko = __double_as_longlong(kd.y);
            {
                double2 q2 = *(const double2*)&q4_s[h][tta][pp];
                ull qe = __double_as_longlong(q2.x);
                ull qo = __double_as_longlong(q2.y);
                ull qen = qen_s[h][tta][pp];
                ull me = m_s[tta][pp][0][sl];
                ull mo = m_s[tta][pp][1][sl];
                ull cc = ffma2(qo, ko, fmul2(qe, ke));
                ull dd = ffma2(qen, ko, fmul2(qo, ke));
                a0 = ffma2(me, cc, a0);
                a0 = ffma2(mo, dd, a0);
            }
            {
                double2 q2 = *(const double2*)&q4_s[h][ttb][pp];
                ull qe = __double_as_longlong(q2.x);
                ull qo = __double_as_longlong(q2.y);
                ull qen = qen_s[h][ttb][pp];
                ull me = m_s[ttb][pp][0][sl];
                ull mo = m_s[ttb][pp][1][sl];
                ull cc = ffma2(qo, ko, fmul2(qe, ke));
                ull dd = ffma2(qen, ko, fmul2(qo, ke));
                a1 = ffma2(me, cc, a1);
                a1 = ffma2(mo, dd, a1);
            }
        }
        float x, y;
        upk2(a0, x, y); sc[0][c] = (x + y) * 0.125f + pm;
        upk2(a1, x, y); sc[1][c] = (x + y) * 0.125f + pm;
    }

    const unsigned FULL = 0xffffffffu;
    float aval[2][8];
#pragma unroll
    for (int u = 0; u < 2; u++) {
        float mx = -CUDART_INF_F;
#pragma unroll
        for (int c = 0; c < 8; c++) mx = fmaxf(mx, sc[u][c]);
#pragma unroll
        for (int o = 16; o > 0; o >>= 1) mx = fmaxf(mx, __shfl_xor_sync(FULL, mx, o));
        float sum = 0.f;
#pragma unroll
        for (int c = 0; c < 8; c++) {
            float e = __expf(sc[u][c] - mx);
            aval[u][c] = e;
            sum += e;
        }
#pragma unroll
        for (int o = 16; o > 0; o >>= 1) sum += __shfl_xor_sync(FULL, sum, o);
        float r = 1.f / sum;
#pragma unroll
        for (int c = 0; c < 8; c++) aval[u][c] *= r;
    }

    __syncthreads();
#pragma unroll
    for (int u = 0; u < 2; u++)
#pragma unroll
        for (int c = 0; c < 8; c++)
            av_s[((2 * g + u) * 8 + h) * 256 + c * 32 + sl] = aval[u][c];
    __syncthreads();

    const float* avh0 = av_s + (tta * 8 + h) * 256;
    const float* avh1 = av_s + (ttb * 8 + h) * 256;
    ull o0a = pk2(0.f, 0.f), o0b = o0a, o1a = o0a, o1b = o0a;
#pragma unroll 4
    for (int s2 = 0; s2 < 256; s2 += 2) {
        ull v0 = *(const ull*)(vbase + (size_t)s2 * D_ + 2 * sl);
        ull v1 = *(const ull*)(vbase + (size_t)(s2 + 1) * D_ + 2 * sl);
        float a00 = avh0[s2], a01 = avh0[s2 + 1];
        float a10 = avh1[s2], a11 = avh1[s2 + 1];
        o0a = ffma2(pk2(a00, a00), v0, o0a);
        o0b = ffma2(pk2(a01, a01), v1, o0b);
        o1a = ffma2(pk2(a10, a10), v0, o1a);
        o1b = ffma2(pk2(a11, a11), v1, o1b);
    }
    ull oa0 = fadd2(o0a, o0b), oa1 = fadd2(o1a, o1b);
    *(ull*)&g_o[((size_t)(b * T_ + t0 + tta) * H_ + h) * D_ + 2 * sl] = oa0;
    *(ull*)&g_o[((size_t)(b * T_ + t0 + ttb) * H_ + h) * D_ + 2 * sl] = oa1;

#pragma unroll
    for (int it = 0; it < 2; it++) {
        int idx = it * 512 + tid;
        int tt = idx >> 8, s5 = idx & 255;
        float acc = 0.f;
#pragma unroll
        for (int hh = 0; hh < 8; hh++) acc += av_s[(tt * 8 + hh) * 256 + s5];
        outw[AW_OFF + (size_t)(b * T_ + t0 + tt) * T_ + s5] = acc * 0.125f;
    }
}

// ---------------------------------------------------------------------------
extern "C" void kernel_launch(void* const* d_in, const int* in_sizes, int n_in,
                              void* d_out, int out_size)
{
    const float* x    = (const float*)d_in[0];
    const float* am   = (const float*)d_in[1];
    const float* pm   = (const float*)d_in[2];
    const float* Wqkv = (const float*)d_in[3];
    const float* bqkv = (const float*)d_in[4];
    const float* Wo   = (const float*)d_in[5];
    const float* bo   = (const float*)d_in[6];
    float* out = (float*)d_out;

    // 1: pre-fill q/k/v with bias (split-K atomic targets)
    init_qkv_kernel<<<1024, 256>>>(bqkv);
    // 2: QKV projection, split-K=2, atomic scatter into q/k/v layouts
    gemm_kernel<64, 4><<<dim3(24, 8, 2), 256>>>(x, Wqkv, nullptr, 1536, 3, 16);
    // 3: fused rotary attention (+ attn_weights region of output)
    attn_kernel<<<128, 512>>>(am, pm, out);
    // 4: pre-fill o-region of output with bias
    init_out_kernel<<<256, 256>>>(bo, out);
    // 5: output projection, split-K=4, atomic accumulate
    gemm_kernel<64, 4><<<dim3(8, 8, 4), 256>>>(nullptr, Wo, out, 512, 2, 8);
}

// round 13
// speedup vs baseline: 1.3769x; 1.0575x over previous
#include <cuda_runtime.h>
#include <math_constants.h>

typedef unsigned long long ull;

#define B_ 2
#define T_ 256
#define E_ 512
#define H_ 8
#define D_ 64
#define AW_OFF (B_*T_*E_)

// scratch (allocation-free: device globals)
__device__ float g_q[B_*H_*T_*D_];        // [b][h][t][pp][4] : (e_p, e_p+16, o_p, o_p+16)
__device__ float g_k[B_*H_*16*T_*4];      // [b][h][pp][s][4] : transposed, coalesced in s
__device__ float g_v[B_*H_*T_*D_];        // natural [b][h][s][d]
__device__ float g_o[B_*T_*E_];           // [b*T+t][h*64+d]

// ---- packed f32x2 helpers -------------------------------------------------
__device__ __forceinline__ ull pk2(float lo, float hi) {
    ull r; asm("mov.b64 %0,{%1,%2};" : "=l"(r) : "f"(lo), "f"(hi)); return r;
}
__device__ __forceinline__ void upk2(ull v, float& a, float& b) {
    asm("mov.b64 {%0,%1},%2;" : "=f"(a), "=f"(b) : "l"(v));
}
__device__ __forceinline__ ull ffma2(ull a, ull b, ull c) {
    ull d; asm("fma.rn.f32x2 %0,%1,%2,%3;" : "=l"(d) : "l"(a), "l"(b), "l"(c)); return d;
}
__device__ __forceinline__ ull fmul2(ull a, ull b) {
    ull d; asm("mul.rn.f32x2 %0,%1,%2;" : "=l"(d) : "l"(a), "l"(b)); return d;
}
__device__ __forceinline__ ull fadd2(ull a, ull b) {
    ull d; asm("add.rn.f32x2 %0,%1,%2;" : "=l"(d) : "l"(a), "l"(b)); return d;
}

// ---------------------------------------------------------------------------
// init: pre-fill g_q/g_k/g_v (scattered bias) AND out o-region (bias).
// 327680 threads: [0,262144) qkv items, [262144,327680) out float4s.
// ---------------------------------------------------------------------------
__global__ void init_kernel(const float* __restrict__ bqkv,
                            const float* __restrict__ bo,
                            float* __restrict__ out)
{
    int idx = blockIdx.x * 256 + threadIdx.x;
    if (idx < 262144) {
        int d = idx & 63;
        int h = (idx >> 14) & 7;
        int hd = h * 64 + d;
        g_v[idx] = bqkv[1024 + hd];
        int base = idx & ~63;                           // ((b*8+h)*256+t)*64
        int p = d >> 1, cmp = d & 1, pp = p & 15, hf = p >> 4;
        g_q[base + pp * 4 + cmp * 2 + hf] = bqkv[hd];
        int t = (idx >> 6) & 255;
        int bh = idx >> 14;                             // b*8+h
        g_k[((bh * 16 + pp) * 256 + t) * 4 + cmp * 2 + hf] = bqkv[512 + hd];
    } else {
        int i2 = idx - 262144;                          // 65536 float4s
        ((float4*)out)[i2] = ((const float4*)bo)[i2 & 127];
    }
}

// ---------------------------------------------------------------------------
// GEMM: C = A @ W. 256 threads, BMx64 tile, BK=16, double-buffered smem,
// microtile TM x 4 cols (2 packed n-pairs). Split-K: kb = blockIdx.z*nk16*16.
// mode 2: atomicAdd into Cout (N=512, A=g_o; bias pre-filled).
// mode 3: atomicAdd scatter into g_q/g_k/g_v (N=1536; bias pre-filled).
// ---------------------------------------------------------------------------
template<int BM, int TM>
__global__ __launch_bounds__(256) void gemm_kernel(const float* __restrict__ A,
                            const float* __restrict__ W,
                            float* __restrict__ Cout,
                            int N, int mode, int nk16)
{
    __shared__ float As[2][16][BM + 4];
    __shared__ float Bs[2][16][64];

    const float* Asrc = (mode == 3) ? A : g_o;

    int tid = threadIdx.x;
    int tx = tid & 15;         // 16 col-groups of 4 (2 packed pairs)
    int ty = tid >> 4;         // 16 row-groups of TM
    int m0 = blockIdx.y * BM, n0 = blockIdx.x * 64;
    int kb = blockIdx.z * nk16 * 16;

    int arow = tid >> 2, ac4 = (tid & 3) * 4;   // A loader (arow < BM active)
    int brow = tid >> 4, bc4 = (tid & 15) * 4;  // B loader

    ull acc[TM][2];
#pragma unroll
    for (int i = 0; i < TM; i++) { acc[i][0] = pk2(0.f, 0.f); acc[i][1] = acc[i][0]; }

    float4 ra, rb;
    if (arow < BM) ra = *(const float4*)&Asrc[(size_t)(m0 + arow) * 512 + kb + ac4];
    rb = *(const float4*)&W[(size_t)(kb + brow) * N + n0 + bc4];
    if (arow < BM) {
        As[0][ac4 + 0][arow] = ra.x; As[0][ac4 + 1][arow] = ra.y;
        As[0][ac4 + 2][arow] = ra.z; As[0][ac4 + 3][arow] = ra.w;
    }
    *(float4*)&Bs[0][brow][bc4] = rb;
    __syncthreads();

    for (int kt16 = 0; kt16 < nk16; kt16++) {
        int cur = kt16 & 1;
        if (kt16 < nk16 - 1) {
            int kt = kb + (kt16 + 1) * 16;
            if (arow < BM) ra = *(const float4*)&Asrc[(size_t)(m0 + arow) * 512 + kt + ac4];
            rb = *(const float4*)&W[(size_t)(kt + brow) * N + n0 + bc4];
        }
#pragma unroll
        for (int kk = 0; kk < 16; kk++) {
            float ar[TM];
            if (TM == 4) {
                float4 a4 = *(const float4*)&As[cur][kk][ty * 4];
                ar[0] = a4.x; ar[1] = a4.y; ar[2] = a4.z; ar[3] = a4.w;
            } else {
                float2 a2 = *(const float2*)&As[cur][kk][ty * 2];
                ar[0] = a2.x; ar[1] = a2.y;
            }
            double2 b2 = *(const double2*)&Bs[cur][kk][tx * 4];
            ull bp0 = __double_as_longlong(b2.x);
            ull bp1 = __double_as_longlong(b2.y);
#pragma unroll
            for (int i = 0; i < TM; i++) {
                ull ad = pk2(ar[i], ar[i]);
                acc[i][0] = ffma2(ad, bp0, acc[i][0]);
                acc[i][1] = ffma2(ad, bp1, acc[i][1]);
            }
        }
        if (kt16 < nk16 - 1) {
            int nxt = cur ^ 1;
            if (arow < BM) {
                As[nxt][ac4 + 0][arow] = ra.x; As[nxt][ac4 + 1][arow] = ra.y;
                As[nxt][ac4 + 2][arow] = ra.z; As[nxt][ac4 + 3][arow] = ra.w;
            }
            *(float4*)&Bs[nxt][brow][bc4] = rb;
        }
        __syncthreads();
    }

    if (mode == 2) {
#pragma unroll
        for (int i = 0; i < TM; i++) {
            int m = m0 + ty * TM + i;
#pragma unroll
            for (int j = 0; j < 2; j++) {
                float x, y; upk2(acc[i][j], x, y);
                int n = n0 + tx * 4 + j * 2;
                atomicAdd(&Cout[(size_t)m * N + n],     x);
                atomicAdd(&Cout[(size_t)m * N + n + 1], y);
            }
        }
    } else {
        int which = n0 >> 9;               // 0=q 1=k 2=v
        int h = (n0 & 511) >> 6;
#pragma unroll
        for (int i = 0; i < TM; i++) {
            int m = m0 + ty * TM + i;
            int b = m >> 8, t = m & 255;
#pragma unroll
            for (int j = 0; j < 2; j++) {
                float x, y; upk2(acc[i][j], x, y);
#pragma unroll
                for (int u = 0; u < 2; u++) {
                    int d = tx * 4 + j * 2 + u;
                    float val = u ? y : x;
                    if (which == 2) {
                        atomicAdd(&g_v[(((size_t)(b * H_ + h) * T_ + t) * D_) + d], val);
                    } else {
                        int p = d >> 1, cmp = d & 1;
                        int pp = p & 15, hf = p >> 4;
                        if (which == 0)
                            atomicAdd(&g_q[(((size_t)(b * H_ + h) * T_ + t) * D_) + pp * 4 + cmp * 2 + hf], val);
                        else
                            atomicAdd(&g_k[((((size_t)(b * H_ + h) * 16 + pp) * T_) + t) * 4 + cmp * 2 + hf], val);
                    }
                }
            }
        }
    }
}

// ---------------------------------------------------------------------------
// Fused rotary attention. grid = 128: (b, 4 t-rows). 512 threads: warp=(g,h).
// qen computed by sign-flip (no smem); A*V reads av pairs as uniform LDS.64.
// Score per pair p:  m_e*(q_e k_e + q_o k_o) + m_o*(q_o k_e - q_e k_o)
// ---------------------------------------------------------------------------
__global__ __launch_bounds__(512) void attn_kernel(const float* __restrict__ mglob,
                            const float* __restrict__ pad,
                            float* __restrict__ outw)
{
    __shared__ ull m_s[4][16][2][33];     // padded lane dim: STS 8-way -> 2-way
    __shared__ float4 q4_s[8][4][16];
    float* av_s = (float*)m_s;            // reused as av[4tt][8h][256s]

    const ull SGN2 = 0x8000000080000000ULL;

    int tid = threadIdx.x;
    int sl = tid & 31;
    int h  = (tid >> 5) & 7;
    int g  = tid >> 8;
    int b  = blockIdx.x >> 6;
    int t0 = (blockIdx.x & 63) * 4;

    {
        int hh = tid >> 6, tt = (tid >> 4) & 3, pp = tid & 15;
        q4_s[hh][tt][pp] = *(const float4*)&g_q[(((size_t)(b * H_ + hh) * T_) + (t0 + tt)) * D_ + pp * 4];
    }

    const double2* kT = (const double2*)g_k + (size_t)(b * H_ + h) * 16 * T_;
    const float*   vbase = g_v + (size_t)(b * H_ + h) * T_ * D_;
    const float*   mbase = mglob + (size_t)(b * T_ + t0) * T_ * D_;

    int j4h_[2], si_[2], tt_[2];
#pragma unroll
    for (int it = 0; it < 2; it++) {
        int idx = it * 512 + tid;
        j4h_[it] = idx & 7; si_[it] = (idx >> 3) & 31; tt_[it] = idx >> 8;
    }

    float4 rv1[2], rv2[2];
#pragma unroll
    for (int it = 0; it < 2; it++) {
        const float* row = mbase + ((size_t)tt_[it] * T_ + si_[it]) * D_;
        rv1[it] = *(const float4*)(row + j4h_[it] * 4);
        rv2[it] = *(const float4*)(row + (j4h_[it] + 8) * 4);
    }

    int tta = 2 * g, ttb = 2 * g + 1;
    float sc[2][8];

#pragma unroll
    for (int c = 0; c < 8; c++) {
        __syncthreads();
#pragma unroll
        for (int it = 0; it < 2; it++) {
            int p0 = 2 * j4h_[it], p1 = p0 + 1, tt = tt_[it], si = si_[it];
            m_s[tt][p0][0][si] = pk2(rv1[it].x, rv2[it].x);
            m_s[tt][p0][1][si] = pk2(rv1[it].y, rv2[it].y);
            m_s[tt][p1][0][si] = pk2(rv1[it].z, rv2[it].z);
            m_s[tt][p1][1][si] = pk2(rv1[it].w, rv2[it].w);
        }
        if (c < 7) {
#pragma unroll
            for (int it = 0; it < 2; it++) {
                const float* row = mbase + ((size_t)tt_[it] * T_ + (c + 1) * 32 + si_[it]) * D_;
                rv1[it] = *(const float4*)(row + j4h_[it] * 4);
                rv2[it] = *(const float4*)(row + (j4h_[it] + 8) * 4);
            }
        }
        __syncthreads();

        int s = c * 32 + sl;
        float pm = pad[b * T_ + s];
        ull a0 = pk2(0.f, 0.f), a1 = a0;
#pragma unroll
        for (int pp = 0; pp < 16; pp++) {
            double2 kd = kT[pp * T_ + s];
            ull ke = __double_as_longlong(kd.x);
            ull ko = __double_as_longlong(kd.y);
            {
                double2 q2 = *(const double2*)&q4_s[h][tta][pp];
                ull qe = __double_as_longlong(q2.x);
                ull qo = __double_as_longlong(q2.y);
                ull qen = qe ^ SGN2;                 // -q_e (alu pipe, no LDS)
                ull me = m_s[tta][pp][0][sl];
                ull mo = m_s[tta][pp][1][sl];
                ull cc = ffma2(qo, ko, fmul2(qe, ke));
                ull dd = ffma2(qen, ko, fmul2(qo, ke));
                a0 = ffma2(me, cc, a0);
                a0 = ffma2(mo, dd, a0);
            }
            {
                double2 q2 = *(const double2*)&q4_s[h][ttb][pp];
                ull qe = __double_as_longlong(q2.x);
                ull qo = __double_as_longlong(q2.y);
                ull qen = qe ^ SGN2;
                ull me = m_s[ttb][pp][0][sl];
                ull mo = m_s[ttb][pp][1][sl];
                ull cc = ffma2(qo, ko, fmul2(qe, ke));
                ull dd = ffma2(qen, ko, fmul2(qo, ke));
                a1 = ffma2(me, cc, a1);
                a1 = ffma2(mo, dd, a1);
            }
        }
        float x, y;
        upk2(a0, x, y); sc[0][c] = (x + y) * 0.125f + pm;
        upk2(a1, x, y); sc[1][c] = (x + y) * 0.125f + pm;
    }

    const unsigned FULL = 0xffffffffu;
    float aval[2][8];
#pragma unroll
    for (int u = 0; u < 2; u++) {
        float mx = -CUDART_INF_F;
#pragma unroll
        for (int c = 0; c < 8; c++) mx = fmaxf(mx, sc[u][c]);
#pragma unroll
        for (int o = 16; o > 0; o >>= 1) mx = fmaxf(mx, __shfl_xor_sync(FULL, mx, o));
        float sum = 0.f;
#pragma unroll
        for (int c = 0; c < 8; c++) {
            float e = __expf(sc[u][c] - mx);
            aval[u][c] = e;
            sum += e;
        }
#pragma unroll
        for (int o = 16; o > 0; o >>= 1) sum += __shfl_xor_sync(FULL, sum, o);
        float r = 1.f / sum;
#pragma unroll
        for (int c = 0; c < 8; c++) aval[u][c] *= r;
    }

    __syncthreads();
#pragma unroll
    for (int u = 0; u < 2; u++)
#pragma unroll
        for (int c = 0; c < 8; c++)
            av_s[((2 * g + u) * 8 + h) * 256 + c * 32 + sl] = aval[u][c];
    __syncthreads();

    const float* avh0 = av_s + (tta * 8 + h) * 256;
    const float* avh1 = av_s + (ttb * 8 + h) * 256;
    ull o0a = pk2(0.f, 0.f), o0b = o0a, o1a = o0a, o1b = o0a;
#pragma unroll 4
    for (int s2 = 0; s2 < 256; s2 += 2) {
        ull v0 = *(const ull*)(vbase + (size_t)s2 * D_ + 2 * sl);
        ull v1 = *(const ull*)(vbase + (size_t)(s2 + 1) * D_ + 2 * sl);
        ull ap0 = *(const ull*)(avh0 + s2);       // uniform LDS.64: (a[s2], a[s2+1])
        ull ap1 = *(const ull*)(avh1 + s2);
        float a00, a01, a10, a11;
        upk2(ap0, a00, a01);
        upk2(ap1, a10, a11);
        o0a = ffma2(pk2(a00, a00), v0, o0a);
        o0b = ffma2(pk2(a01, a01), v1, o0b);
        o1a = ffma2(pk2(a10, a10), v0, o1a);
        o1b = ffma2(pk2(a11, a11), v1, o1b);
    }
    ull oa0 = fadd2(o0a, o0b), oa1 = fadd2(o1a, o1b);
    *(ull*)&g_o[((size_t)(b * T_ + t0 + tta) * H_ + h) * D_ + 2 * sl] = oa0;
    *(ull*)&g_o[((size_t)(b * T_ + t0 + ttb) * H_ + h) * D_ + 2 * sl] = oa1;

#pragma unroll
    for (int it = 0; it < 2; it++) {
        int idx = it * 512 + tid;
        int tt = idx >> 8, s5 = idx & 255;
        float acc = 0.f;
#pragma unroll
        for (int hh = 0; hh < 8; hh++) acc += av_s[(tt * 8 + hh) * 256 + s5];
        outw[AW_OFF + (size_t)(b * T_ + t0 + tt) * T_ + s5] = acc * 0.125f;
    }
}

// ---------------------------------------------------------------------------
extern "C" void kernel_launch(void* const* d_in, const int* in_sizes, int n_in,
                              void* d_out, int out_size)
{
    const float* x    = (const float*)d_in[0];
    const float* am   = (const float*)d_in[1];
    const float* pm   = (const float*)d_in[2];
    const float* Wqkv = (const float*)d_in[3];
    const float* bqkv = (const float*)d_in[4];
    const float* Wo   = (const float*)d_in[5];
    const float* bo   = (const float*)d_in[6];
    float* out = (float*)d_out;

    // 1: pre-fill q/k/v (scattered bias) and out o-region (bias)
    init_kernel<<<1280, 256>>>(bqkv, bo, out);
    // 2: QKV projection, split-K=2, atomic scatter into q/k/v layouts
    gemm_kernel<64, 4><<<dim3(24, 8, 2), 256>>>(x, Wqkv, nullptr, 1536, 3, 16);
    // 3: fused rotary attention (+ attn_weights region of output)
    attn_kernel<<<128, 512>>>(am, pm, out);
    // 4: output projection, split-K=4, atomic accumulate
    gemm_kernel<64, 4><<<dim3(8, 8, 4), 256>>>(nullptr, Wo, out, 512, 2, 8);
}